// round 15
// baseline (speedup 1.0000x reference)
#include <cuda_runtime.h>
#include <cstdint>

// CASSI forward: fused dual-pipeline block (one block per m row, 256 thr).
// Warpgroup 0 computes c in [0,512), warpgroup 1 computes c in [512,1087),
// each with its own 2-deep TMA ring and named-barrier tile sync (decoupled).
// The diagonal carry crossing n=512 is exchanged through smem at the end:
// h1 holds its tile-0 accL in a register; after __syncthreads it adds h0's
// final carry and stores. No halo, no atomics, no zero-init, one launch.
//
// Per tile (TN=128 n-rows, 32KB): thread wtid accumulates
//   accL -> output c = n0 + t*128 + wtid  (terms l <= wtid)
//   accH -> carry for next tile           (terms l >  wtid)

#define MM    1024
#define NN    1024
#define LL    64
#define OUTC  (NN + LL - 1)            // 1087
#define TN    128
#define TPB   256
#define HALF  512
#define NTIL  (HALF / TN)              // 4
#define TILE_BYTES (TN * LL * 4)       // 32768

__device__ __forceinline__ uint32_t smem_u32(const void* p)
{
    uint32_t a;
    asm("{ .reg .u64 t; cvta.to.shared.u64 t, %1; cvt.u32.u64 %0, t; }"
        : "=r"(a) : "l"(p));
    return a;
}

__device__ __forceinline__ void mbar_init(uint32_t mb, uint32_t count)
{
    asm volatile("mbarrier.init.shared.b64 [%0], %1;" :: "r"(mb), "r"(count) : "memory");
}

__device__ __forceinline__ void tma_bulk(uint32_t dst, const float* src,
                                         uint32_t bytes, uint32_t mb)
{
    asm volatile("mbarrier.arrive.expect_tx.shared.b64 _, [%0], %1;"
                 :: "r"(mb), "r"(bytes) : "memory");
    asm volatile("cp.async.bulk.shared::cta.global.mbarrier::complete_tx::bytes "
                 "[%0], [%1], %2, [%3];"
                 :: "r"(dst), "l"(src), "r"(bytes), "r"(mb) : "memory");
}

__device__ __forceinline__ void mbar_wait(uint32_t mb, uint32_t parity)
{
    uint32_t done;
    asm volatile(
        "{\n\t"
        ".reg .pred p;\n\t"
        "mbarrier.try_wait.parity.acquire.cta.shared::cta.b64 p, [%1], %2;\n\t"
        "selp.b32 %0, 1, 0, p;\n\t"
        "}"
        : "=r"(done) : "r"(mb), "r"(parity) : "memory");
    if (!done) {
        asm volatile(
            "{\n\t"
            ".reg .pred P1;\n\t"
            "W%=:\n\t"
            "mbarrier.try_wait.parity.acquire.cta.shared::cta.b64 P1, [%0], %1;\n\t"
            "@P1 bra D%=;\n\t"
            "bra W%=;\n\t"
            "D%=:\n\t"
            "}"
            :: "r"(mb), "r"(parity) : "memory");
    }
}

// per-warpgroup barrier (128 threads), ids 1 and 2
__device__ __forceinline__ void wg_bar(int id)
{
    asm volatile("bar.sync %0, 128;" :: "r"(id) : "memory");
}

__global__ __launch_bounds__(TPB)
void cassi_fused_kernel(const float* __restrict__ x,
                        const float* __restrict__ ca,
                        float* __restrict__ y)
{
    extern __shared__ float smem[];
    // layout: 4 tile buffers (wg0: 0,1  wg1: 2,3), then sca[2][512], then cx[64]
    float* sca_all = smem + 4 * TN * LL;
    float* cx      = sca_all + 2 * HALF;
    __shared__ __align__(8) uint64_t mbar_store[4];

    const int m    = blockIdx.x;
    const int tid  = threadIdx.x;
    const int wg   = tid >> 7;                 // 0: c in [0,512), 1: [512,1087)
    const int wtid = tid & 127;
    const int n0   = wg * HALF;

    float* buf0 = smem + (2 * wg + 0) * TN * LL;
    float* buf1 = smem + (2 * wg + 1) * TN * LL;
    float* sca  = sca_all + wg * HALF;

    const float* xrow  = x + ((size_t)m * NN + n0) * LL;
    const float* carow = ca + m * NN;
    float*       yrow  = y + (size_t)m * OUTC;

    const uint32_t mb0 = smem_u32(&mbar_store[2 * wg + 0]);
    const uint32_t mb1 = smem_u32(&mbar_store[2 * wg + 1]);
    const uint32_t b0  = smem_u32(buf0);
    const uint32_t b1  = smem_u32(buf1);

    if (tid == 0) {
        #pragma unroll
        for (int i = 0; i < 4; ++i) mbar_init(smem_u32(&mbar_store[i]), 1);
    }
    __syncthreads();

    if (wtid == 0) {
        tma_bulk(b0, xrow,           TILE_BYTES, mb0);
        tma_bulk(b1, xrow + TN * LL, TILE_BYTES, mb1);
    }

    // Stage ca for this half (one float4 per thread).
    ((float4*)sca)[wtid] = ((const float4*)(carow + n0))[wtid];
    wg_bar(wg + 1);

    float carry = 0.0f;
    float accL0 = 0.0f;                        // h1's deferred tile-0 result

    #pragma unroll 1
    for (int t = 0; t < NTIL; ++t) {
        const uint32_t mb     = (t & 1) ? mb1 : mb0;
        const float*   cur    = (t & 1) ? buf1 : buf0;
        const uint32_t parity = (t >> 1) & 1;

        mbar_wait(mb, parity);

        const float* scat = sca + t * TN;
        float accL = carry;                    // carry == 0 for wtid >= LL-1
        float accH = 0.0f;
        #pragma unroll
        for (int j = 0; j < LL; ++j) {
            const int  l   = (wtid + j) & (LL - 1);
            const bool low = (l <= wtid);
            const int  n   = low ? (wtid - l) : (wtid + TN - l);
            const float v  = cur[n * LL + l];
            if (low) accL = fmaf(v, scat[n], accL);
            else     accH = fmaf(v, scat[n], accH);
        }
        if (wg == 1 && t == 0)
            accL0 = accL;                      // completed after carry exchange
        else
            yrow[n0 + t * TN + wtid] = accL;
        carry = accH;

        wg_bar(wg + 1);                        // this wg done reading `cur`

        if (wtid == 0 && t + 2 < NTIL) {
            const uint32_t db = (t & 1) ? b1 : b0;
            tma_bulk(db, xrow + (size_t)(t + 2) * TN * LL, TILE_BYTES, mb);
        }
    }

    // Carry exchange across the n=512 boundary.
    if (wg == 0 && wtid < LL - 1)
        cx[wtid] = carry;                      // h0's terms for c = 512+wtid
    __syncthreads();

    if (wg == 1) {
        // tile-0 outputs c in [512, 640): add h0's boundary carry
        const float add = (wtid < LL - 1) ? cx[wtid] : 0.0f;
        yrow[HALF + wtid] = accL0 + add;
        // tail outputs c in [1024, 1087)
        if (wtid < LL - 1)
            yrow[NN + wtid] = carry;
    }
}

extern "C" void kernel_launch(void* const* d_in, const int* in_sizes, int n_in,
                              void* d_out, int out_size)
{
    const float* x  = (const float*)d_in[0];
    const float* ca = (const float*)d_in[1];
    float* y        = (float*)d_out;

    const int smem_bytes =
        (4 * TN * LL + 2 * HALF + 64) * sizeof(float);   // 135424 B

    cudaFuncSetAttribute(cassi_fused_kernel,
                         cudaFuncAttributeMaxDynamicSharedMemorySize,
                         smem_bytes);

    cassi_fused_kernel<<<MM, TPB, smem_bytes>>>(x, ca, y);
}

// round 16
// speedup vs baseline: 1.5299x; 1.5299x over previous
#include <cuda_runtime.h>
#include <cstdint>

// CASSI forward: asymmetric-stream TMA pipeline, 3 blocks/SM.
//
// Grid (2, 1024). Block (h, m):
//  h=0: streams rows [0,512) in 4 tiles, stores outputs c in [0,512).
//  h=1: streams rows [449,1024) in 5 tiles (last short, 63 rows),
//       stores outputs c in [512,1087). Starting 63 rows early makes
//       tile 0's accL complete for c>=512 with zero carry-in -> NO halo
//       buffer, NO seed reduce. smem = 2x32KB ring + 2.3KB ca = 66.3KB
//       -> 3 blocks/SM (R12 had 2).
// Per tile (TN=128 rows): thread tid computes
//   accL -> output c = row_start + t*128 + tid  (terms l <= tid)
//   accH -> carry for next tile                 (terms l >  tid)

#define MM    1024
#define NN    1024
#define LL    64
#define OUTC  (NN + LL - 1)            // 1087
#define TN    128
#define TPB   128
#define TILE_BYTES (TN * LL * 4)       // 32768
#define H1_START   (NN / 2 - (LL - 1)) // 449
#define H1_ROWS    (NN - H1_START)     // 575
#define LAST_ROWS  (H1_ROWS - 4 * TN)  // 63
#define LAST_BYTES (LAST_ROWS * LL * 4)

__device__ __forceinline__ uint32_t smem_u32(const void* p)
{
    uint32_t a;
    asm("{ .reg .u64 t; cvta.to.shared.u64 t, %1; cvt.u32.u64 %0, t; }"
        : "=r"(a) : "l"(p));
    return a;
}

__device__ __forceinline__ void mbar_init(uint32_t mb, uint32_t count)
{
    asm volatile("mbarrier.init.shared.b64 [%0], %1;" :: "r"(mb), "r"(count) : "memory");
}

__device__ __forceinline__ void tma_bulk(uint32_t dst, const float* src,
                                         uint32_t bytes, uint32_t mb)
{
    asm volatile("mbarrier.arrive.expect_tx.shared.b64 _, [%0], %1;"
                 :: "r"(mb), "r"(bytes) : "memory");
    asm volatile("cp.async.bulk.shared::cta.global.mbarrier::complete_tx::bytes "
                 "[%0], [%1], %2, [%3];"
                 :: "r"(dst), "l"(src), "r"(bytes), "r"(mb) : "memory");
}

__device__ __forceinline__ void mbar_wait(uint32_t mb, uint32_t parity)
{
    uint32_t done;
    asm volatile(
        "{\n\t"
        ".reg .pred p;\n\t"
        "mbarrier.try_wait.parity.acquire.cta.shared::cta.b64 p, [%1], %2;\n\t"
        "selp.b32 %0, 1, 0, p;\n\t"
        "}"
        : "=r"(done) : "r"(mb), "r"(parity) : "memory");
    if (!done) {
        asm volatile(
            "{\n\t"
            ".reg .pred P1;\n\t"
            "W%=:\n\t"
            "mbarrier.try_wait.parity.acquire.cta.shared::cta.b64 P1, [%0], %1;\n\t"
            "@P1 bra D%=;\n\t"
            "bra W%=;\n\t"
            "D%=:\n\t"
            "}"
            :: "r"(mb), "r"(parity) : "memory");
    }
}

__global__ __launch_bounds__(TPB, 3)
void cassi_asym_kernel(const float* __restrict__ x,
                       const float* __restrict__ ca,
                       float* __restrict__ y)
{
    extern __shared__ float smem[];
    float* buf0 = smem;                          // 8192 floats (32KB)
    float* buf1 = buf0 + TN * LL;                // 8192 floats (32KB)
    float* sca  = buf1 + TN * LL;                // up to 575 floats
    __shared__ __align__(8) uint64_t mbar_store[2];

    const int m   = blockIdx.y;
    const int h   = blockIdx.x;                  // 0 or 1
    const int tid = threadIdx.x;

    const int row_start = h ? H1_START : 0;      // first streamed row
    const int nrows     = h ? H1_ROWS  : (NN / 2);
    const int ntiles    = h ? 5 : 4;             // last h1 tile is short

    const float* xrow  = x + ((size_t)m * NN + row_start) * LL;
    const float* carow = ca + m * NN;
    float*       yrow  = y + (size_t)m * OUTC;

    const uint32_t mb0 = smem_u32(&mbar_store[0]);
    const uint32_t mb1 = smem_u32(&mbar_store[1]);
    const uint32_t b0  = smem_u32(buf0);
    const uint32_t b1  = smem_u32(buf1);

    if (tid == 0) {
        mbar_init(mb0, 1);
        mbar_init(mb1, 1);
    }
    __syncthreads();

    if (tid == 0) {
        tma_bulk(b0, xrow,           TILE_BYTES, mb0);
        tma_bulk(b1, xrow + TN * LL, TILE_BYTES, mb1);
    }

    // Stage ca for all streamed rows (coalesced scalar loads).
    for (int i = tid; i < nrows; i += TPB)
        sca[i] = carow[row_start + i];
    __syncthreads();

    float carry = 0.0f;

    // Main loop: 4 full tiles for everyone.
    #pragma unroll 1
    for (int t = 0; t < 4; ++t) {
        const uint32_t mb     = (t & 1) ? mb1 : mb0;
        const float*   cur    = (t & 1) ? buf1 : buf0;
        const uint32_t parity = (t >> 1) & 1;

        mbar_wait(mb, parity);

        const float* scat = sca + t * TN;
        float accL = carry;                      // carry == 0 for tid >= LL-1
        float accH = 0.0f;
        #pragma unroll
        for (int j = 0; j < LL; ++j) {
            const int  l   = (tid + j) & (LL - 1);
            const bool low = (l <= tid);
            const int  n   = low ? (tid - l) : (tid + TN - l);
            const float v  = cur[n * LL + l];
            if (low) accL = fmaf(v, scat[n], accL);
            else     accH = fmaf(v, scat[n], accH);
        }

        __syncthreads();                         // all reads of `cur` done

        if (tid == 0 && t + 2 < ntiles) {
            const uint32_t db    = (t & 1) ? b1 : b0;
            const uint32_t bytes = (h && t + 2 == 4) ? LAST_BYTES : TILE_BYTES;
            tma_bulk(db, xrow + (size_t)(t + 2) * TN * LL, bytes, mb);
        }

        // Store: h0 keeps everything; h1's tile 0 keeps only c >= 512
        // (tid >= 63) -- smaller tids' outputs belong to h0.
        const int c = row_start + t * TN + tid;
        if (h == 0 || t > 0 || tid >= LL - 1)
            yrow[c] = accL;
        carry = accH;
    }

    // h1 epilogue: short tile 4 (rows [961,1024), 63 rows in buf0).
    if (h == 1) {
        mbar_wait(mb0, /*parity for 3rd use of mb0*/ 0 ^ 1 ^ 1);  // t=4 -> parity 0
        const float* cur  = buf0;
        const float* scat = sca + 4 * TN;        // rows 961+
        float acc = carry;
        #pragma unroll
        for (int j = 0; j < LL; ++j) {
            const int l = (tid + j) & (LL - 1);
            const int n = tid - l;
            if (l <= tid && n < LAST_ROWS)       // only 63 valid rows
                acc = fmaf(cur[n * LL + l], scat[n], acc);
        }
        const int c = row_start + 4 * TN + tid;  // 961 + tid
        if (c < OUTC)                            // c <= 1086 -> tid <= 125
            yrow[c] = acc;
    }
}

extern "C" void kernel_launch(void* const* d_in, const int* in_sizes, int n_in,
                              void* d_out, int out_size)
{
    const float* x  = (const float*)d_in[0];
    const float* ca = (const float*)d_in[1];
    float* y        = (float*)d_out;

    const int smem_bytes = (2 * TN * LL + H1_ROWS + 1) * sizeof(float); // 67840 B

    cudaFuncSetAttribute(cassi_asym_kernel,
                         cudaFuncAttributeMaxDynamicSharedMemorySize,
                         smem_bytes);

    cassi_asym_kernel<<<dim3(2, MM), TPB, smem_bytes>>>(x, ca, y);
}